// round 9
// baseline (speedup 1.0000x reference)
#include <cuda_runtime.h>
#include <cstdint>

// Segment-mean over sorted segment ids, two-phase with PDL overlap:
//   A) int4-vectorized streaming boundary scan builds seg_start[]
//   B) FOUR molecules per 256-thread CTA (two fused proven 2-mol units),
//      one barrier per CTA, streaming cache hints, PDL-launched.
// atom_hiddens: [n_atoms, 128] f32 ; segment_ids: [n_atoms] i32 (sorted) ;
// out: [n_mols, 128] f32.

static constexpr int HIDDEN = 128;
static constexpr int MAX_MOLS = 4 * 1024 * 1024;   // scratch capacity (16 MB)

__device__ int g_seg_start[MAX_MOLS + 1];

// ---- Kernel A: find segment boundaries (int4-vectorized pass over ids) ----
__global__ __launch_bounds__(256)
void seg_offsets_kernel(const int* __restrict__ ids, int n_atoms, int n_mols) {
    const int base = (blockIdx.x * 256 + threadIdx.x) * 4;

    if (base < n_atoms) {
        if (base == 0) {
            g_seg_start[__ldg(ids)] = 0;       // first segment start
            g_seg_start[n_mols] = n_atoms;     // sentinel
        }

        if (base + 3 < n_atoms) {
            const int4 v = __ldcs(reinterpret_cast<const int4*>(ids + base));
            if (base > 0 && v.x != __ldg(ids + base - 1)) g_seg_start[v.x] = base;
            if (v.y != v.x) g_seg_start[v.y] = base + 1;
            if (v.z != v.y) g_seg_start[v.z] = base + 2;
            if (v.w != v.z) g_seg_start[v.w] = base + 3;
        } else {
            for (int i = base; i < n_atoms; ++i) {
                if (i > 0 && __ldg(ids + i) != __ldg(ids + i - 1))
                    g_seg_start[__ldg(ids + i)] = i;
            }
        }
    }

    // All boundary stores above are visible to the dependent grid after this.
    asm volatile("griddepcontrol.launch_dependents;");
}

// ---- Kernel B: four molecules per 256-thread CTA, single barrier ----
__global__ __launch_bounds__(256)
void seg_mean_kernel(const float* __restrict__ x,
                     float*       __restrict__ out,
                     int n_mols) {
    const int t     = threadIdx.x;
    const int warp  = t >> 5;          // 0..7
    const int lane  = t & 31;
    const int group = warp >> 2;       // 0 or 1: which 2-mol unit
    const int wg    = warp & 3;        // warp within unit
    const int mol0  = blockIdx.x * 4;  // first of 4 molecules

    // s_part[mol_local][warp_in_unit][col]
    __shared__ alignas(16) float s_part[4][4][HIDDEN];

    // Block until kernel A's boundary writes are visible (PDL handshake).
    asm volatile("griddepcontrol.wait;" ::: "memory");

    // This unit's two molecules (guard the tail CTA).
    const int mA = mol0 + 2 * group;        // first molecule of this unit
    const int mB = mA + 1;

    const int sA = (mA < n_mols) ? __ldg(&g_seg_start[mA])     : 0;
    const int eA = (mA < n_mols) ? __ldg(&g_seg_start[mA + 1]) : 0;
    const int eB = (mB < n_mols) ? __ldg(&g_seg_start[mB + 1]) : eA;

    const float4* __restrict__ xv = reinterpret_cast<const float4*>(x) + lane;

    // Warp wg covers rows start+wg, start+wg+4, ... ; evict-first loads.
    float4 a0 = make_float4(0.f, 0.f, 0.f, 0.f);
    float4 a1 = make_float4(0.f, 0.f, 0.f, 0.f);

    #pragma unroll 5
    for (int r = sA + wg; r < eA; r += 4) {
        const float4 v = __ldcs(xv + (size_t)r * 32);
        a0.x += v.x; a0.y += v.y; a0.z += v.z; a0.w += v.w;
    }
    #pragma unroll 5
    for (int r = eA + wg; r < eB; r += 4) {
        const float4 v = __ldcs(xv + (size_t)r * 32);
        a1.x += v.x; a1.y += v.y; a1.z += v.z; a1.w += v.w;
    }

    *reinterpret_cast<float4*>(&s_part[2 * group    ][wg][lane * 4]) = a0;
    *reinterpret_cast<float4*>(&s_part[2 * group + 1][wg][lane * 4]) = a1;
    __syncthreads();

    // Epilogue: 256 threads cover 4 mols x 128 cols = 512 outputs, 2 each.
    #pragma unroll
    for (int k = 0; k < 2; ++k) {
        const int ml  = (t >> 7) + 2 * k;   // molecule local index 0..3
        const int col = t & 127;
        const int mol = mol0 + ml;
        if (mol < n_mols) {
            const int st  = __ldg(&g_seg_start[mol]);       // L1-hot
            const int en  = __ldg(&g_seg_start[mol + 1]);
            const int cnt = en - st;
            const float inv = (cnt > 0) ? (1.0f / (float)cnt) : 0.0f;
            const float sum = s_part[ml][0][col] + s_part[ml][1][col]
                            + s_part[ml][2][col] + s_part[ml][3][col];
            __stcs(out + (size_t)mol * HIDDEN + col, sum * inv);
        }
    }
}

extern "C" void kernel_launch(void* const* d_in, const int* in_sizes, int n_in,
                              void* d_out, int out_size) {
    const float* atom_hiddens = (const float*)d_in[0];
    const int*   segment_ids  = (const int*)d_in[1];
    float* out = (float*)d_out;

    const int n_atoms = in_sizes[1];          // segment_ids element count
    const int n_mols  = out_size / HIDDEN;    // output rows

    const int gridA = (n_atoms / 4 + 255) / 256 + 1;
    seg_offsets_kernel<<<gridA, 256>>>(segment_ids, n_atoms, n_mols);

    // Kernel B with programmatic dependent launch (overlaps launch with A).
    const int gridB = (n_mols + 3) / 4;

    cudaLaunchConfig_t cfg = {};
    cfg.gridDim  = dim3((unsigned)gridB, 1, 1);
    cfg.blockDim = dim3(256, 1, 1);
    cfg.dynamicSmemBytes = 0;
    cfg.stream = 0;

    cudaLaunchAttribute attrs[1];
    attrs[0].id = cudaLaunchAttributeProgrammaticStreamSerialization;
    attrs[0].val.programmaticStreamSerializationAllowed = 1;
    cfg.attrs = attrs;
    cfg.numAttrs = 1;

    cudaError_t err = cudaLaunchKernelEx(&cfg, seg_mean_kernel,
                                         atom_hiddens, out, n_mols);
    if (err != cudaSuccess) {
        // Fallback: plain launch (griddepcontrol.wait is a no-op without PDL).
        seg_mean_kernel<<<gridB, 256>>>(atom_hiddens, out, n_mols);
    }
}